// round 3
// baseline (speedup 1.0000x reference)
#include <cuda_runtime.h>
#include <cuda_bf16.h>
#include <cstdint>

#define MAX_NODES 100000
#define D 128

// Scratch (no allocations allowed): h_scaled rows, degree arrays.
__device__ float g_h[MAX_NODES * D];       // (x@W + b) * rsqrt(max(deg_s,1))
__device__ float g_deg_s[MAX_NODES];
__device__ float g_deg_r[MAX_NODES];

// ---------------------------------------------------------------------------
// Zero d_out (float4) and degree arrays. Must run every launch (graph replay).
// ---------------------------------------------------------------------------
__global__ void zero_out_kernel(float4* __restrict__ out, int n4) {
    int i = blockIdx.x * blockDim.x + threadIdx.x;
    if (i < n4) out[i] = make_float4(0.f, 0.f, 0.f, 0.f);
}

__global__ void zero_deg_kernel(int n) {
    int i = blockIdx.x * blockDim.x + threadIdx.x;
    if (i < n) { g_deg_s[i] = 0.f; g_deg_r[i] = 0.f; }
}

// ---------------------------------------------------------------------------
// Degree counts: one thread per edge, two float atomics.
// ---------------------------------------------------------------------------
__global__ void degree_kernel(const int* __restrict__ s,
                              const int* __restrict__ r, int E) {
    int i = blockIdx.x * blockDim.x + threadIdx.x;
    if (i < E) {
        atomicAdd(&g_deg_s[s[i]], 1.0f);
        atomicAdd(&g_deg_r[r[i]], 1.0f);
    }
}

// ---------------------------------------------------------------------------
// GEMM + pre-scale epilogue.
// Tile: BM=64 rows x BN=128 cols (full N), BK=16. 256 threads.
// Thread (rg,cg): rg=tid/16 owns 4 rows, cg=tid%16 owns 8 cols -> 4x8 acc.
// ---------------------------------------------------------------------------
__global__ __launch_bounds__(256) void gemm_scale_kernel(
    const float* __restrict__ x, const float* __restrict__ w,
    const float* __restrict__ bias, int M) {

    __shared__ float xs[16][64];    // [k][row]
    __shared__ float ws[16][128];   // [k][col]

    const int t  = threadIdx.x;
    const int rg = t >> 4;          // 0..15  -> rows rg*4..rg*4+3
    const int cg = t & 15;          // 0..15  -> cols cg*8..cg*8+7
    const int row0 = blockIdx.x * 64;

    const int lr = t >> 2;          // load row 0..63
    const int kq = t & 3;           // k-quad 0..3

    float acc[4][8];
    #pragma unroll
    for (int i = 0; i < 4; i++)
        #pragma unroll
        for (int j = 0; j < 8; j++) acc[i][j] = 0.f;

    for (int k0 = 0; k0 < D; k0 += 16) {
        // x tile: 64 rows x 16 k. Each thread one float4, store transposed.
        {
            int gr = row0 + lr;
            float4 xv = make_float4(0.f, 0.f, 0.f, 0.f);
            if (gr < M)
                xv = *(const float4*)&x[(size_t)gr * D + k0 + kq * 4];
            xs[kq * 4 + 0][lr] = xv.x;
            xs[kq * 4 + 1][lr] = xv.y;
            xs[kq * 4 + 2][lr] = xv.z;
            xs[kq * 4 + 3][lr] = xv.w;
        }
        // w tile: 16 x 128 = 512 float4; 256 threads x 2, coalesced.
        {
            int idx = t;
            int kr = idx >> 5, c4 = idx & 31;
            *(float4*)&ws[kr][c4 * 4] =
                *(const float4*)&w[(size_t)(k0 + kr) * D + c4 * 4];
            idx = t + 256; kr = idx >> 5; c4 = idx & 31;
            *(float4*)&ws[kr][c4 * 4] =
                *(const float4*)&w[(size_t)(k0 + kr) * D + c4 * 4];
        }
        __syncthreads();

        #pragma unroll
        for (int k = 0; k < 16; k++) {
            float4 a  = *(float4*)&xs[k][rg * 4];
            float4 b0 = *(float4*)&ws[k][cg * 8];
            float4 b1 = *(float4*)&ws[k][cg * 8 + 4];
            float av[4] = {a.x, a.y, a.z, a.w};
            float bv[8] = {b0.x, b0.y, b0.z, b0.w, b1.x, b1.y, b1.z, b1.w};
            #pragma unroll
            for (int i = 0; i < 4; i++)
                #pragma unroll
                for (int j = 0; j < 8; j++)
                    acc[i][j] += av[i] * bv[j];
        }
        __syncthreads();
    }

    float bv[8];
    #pragma unroll
    for (int j = 0; j < 8; j++) bv[j] = bias[cg * 8 + j];

    #pragma unroll
    for (int i = 0; i < 4; i++) {
        int row = row0 + rg * 4 + i;
        if (row < M) {
            float sc = rsqrtf(fmaxf(g_deg_s[row], 1.0f));
            #pragma unroll
            for (int j = 0; j < 8; j += 4) {
                float4 v;
                v.x = (acc[i][j + 0] + bv[j + 0]) * sc;
                v.y = (acc[i][j + 1] + bv[j + 1]) * sc;
                v.z = (acc[i][j + 2] + bv[j + 2]) * sc;
                v.w = (acc[i][j + 3] + bv[j + 3]) * sc;
                *(float4*)&g_h[(size_t)row * D + cg * 8 + j] = v;
            }
        }
    }
}

// ---------------------------------------------------------------------------
// Edge scatter: one warp per edge. Lane l moves float4 l of the 128-float row.
// red.global.add.v4.f32: no-return vector reduction (sm_90+), 1/4 the atomic
// op count of scalar atomicAdd.
// ---------------------------------------------------------------------------
__global__ __launch_bounds__(256) void scatter_kernel(
    const int* __restrict__ s, const int* __restrict__ r,
    float* __restrict__ out, int E) {

    int gid  = blockIdx.x * blockDim.x + threadIdx.x;
    int e    = gid >> 5;
    int lane = gid & 31;
    if (e >= E) return;

    int src = __ldg(&s[e]);
    int dst = __ldg(&r[e]);

    float4 v = *(const float4*)&g_h[(size_t)src * D + lane * 4];
    float* op = out + (size_t)dst * D + lane * 4;
    asm volatile("red.global.add.v4.f32 [%0], {%1, %2, %3, %4};"
                 :: "l"(op), "f"(v.x), "f"(v.y), "f"(v.z), "f"(v.w)
                 : "memory");
}

// ---------------------------------------------------------------------------
// Final scale by rsqrt(max(deg_r, 1)).
// ---------------------------------------------------------------------------
__global__ void final_scale_kernel(float4* __restrict__ out, int M) {
    int i = blockIdx.x * blockDim.x + threadIdx.x;   // float4 index
    int n4 = M * (D / 4);
    if (i < n4) {
        int row = i >> 5;                            // D/4 == 32 float4 per row
        float sc = rsqrtf(fmaxf(g_deg_r[row], 1.0f));
        float4 v = out[i];
        v.x *= sc; v.y *= sc; v.z *= sc; v.w *= sc;
        out[i] = v;
    }
}

// ---------------------------------------------------------------------------
// Inputs (metadata order): x[N*128] f32, senders[E] i32, receivers[E] i32,
// n_node i32, weight[128*128] f32, bias[128] f32. Output: [N*128] f32.
// ---------------------------------------------------------------------------
extern "C" void kernel_launch(void* const* d_in, const int* in_sizes, int n_in,
                              void* d_out, int out_size) {
    const float* x       = (const float*)d_in[0];
    const int*   senders = (const int*)  d_in[1];
    const int*   recvs   = (const int*)  d_in[2];
    const float* weight  = (const float*)d_in[4];
    const float* bias    = (const float*)d_in[5];
    float*       out     = (float*)d_out;

    const int N = in_sizes[0] / D;
    const int E = in_sizes[1];

    // 1) zero output + degrees (must happen every replay)
    {
        int n4 = N * (D / 4);
        zero_out_kernel<<<(n4 + 255) / 256, 256>>>((float4*)out, n4);
        zero_deg_kernel<<<(N + 255) / 256, 256>>>(N);
    }
    // 2) degrees
    degree_kernel<<<(E + 255) / 256, 256>>>(senders, recvs, E);
    // 3) GEMM + bias + sender-degree pre-scale -> g_h
    gemm_scale_kernel<<<(N + 63) / 64, 256>>>(x, weight, bias, N);
    // 4) edge scatter-sum (warp per edge)
    {
        long long threads = (long long)E * 32;
        int blocks = (int)((threads + 255) / 256);
        scatter_kernel<<<blocks, 256>>>(senders, recvs, out, E);
    }
    // 5) receiver-degree post-scale
    {
        int n4 = N * (D / 4);
        final_scale_kernel<<<(n4 + 255) / 256, 256>>>((float4*)out, N);
    }
}

// round 5
// speedup vs baseline: 1.8579x; 1.8579x over previous
#include <cuda_runtime.h>
#include <cuda_bf16.h>
#include <cstdint>

#define MAX_NODES 100000
#define MAX_EDGES 1600000
#define D 128
#define SCAN_B 512

// ---------------------------------------------------------------------------
// Scratch (device globals; no allocations allowed anywhere).
// ---------------------------------------------------------------------------
__device__ float g_h[MAX_NODES * D];          // (x@W + b) * rsqrt(max(deg_s,1))
__device__ int   g_cnt_s[MAX_NODES];          // sender degree
__device__ int   g_cnt_r[MAX_NODES];          // receiver degree
__device__ int   g_row_ptr[MAX_NODES + 1];    // CSR row pointers (by receiver)
__device__ int   g_cursor[MAX_NODES];         // fill cursors
__device__ int   g_edge_src[MAX_EDGES];       // CSR column indices (sender ids)
__device__ int   g_partial[1024];             // scan block partials

// ---------------------------------------------------------------------------
// 1) zero degree counters (must run every graph replay)
// ---------------------------------------------------------------------------
__global__ void zero_cnt_kernel(int n) {
    int i = blockIdx.x * blockDim.x + threadIdx.x;
    if (i < n) { g_cnt_s[i] = 0; g_cnt_r[i] = 0; }
}

// ---------------------------------------------------------------------------
// 2) degree histogram (int atomics)
// ---------------------------------------------------------------------------
__global__ void hist_kernel(const int* __restrict__ s,
                            const int* __restrict__ r, int E) {
    int i = blockIdx.x * blockDim.x + threadIdx.x;
    if (i < E) {
        atomicAdd(&g_cnt_s[s[i]], 1);
        atomicAdd(&g_cnt_r[r[i]], 1);
    }
}

// ---------------------------------------------------------------------------
// 3) exclusive scan of g_cnt_r -> g_row_ptr  (3 kernels)
// ---------------------------------------------------------------------------
__global__ void scan_part_kernel(int N) {
    __shared__ int sh[SCAN_B];
    int tid = threadIdx.x;
    int i = blockIdx.x * SCAN_B + tid;
    int v = (i < N) ? g_cnt_r[i] : 0;
    sh[tid] = v;
    __syncthreads();
    #pragma unroll
    for (int off = 1; off < SCAN_B; off <<= 1) {
        int t = (tid >= off) ? sh[tid - off] : 0;
        __syncthreads();
        sh[tid] += t;
        __syncthreads();
    }
    if (i < N + 1 && i <= N) {
        if (i < N) g_row_ptr[i] = sh[tid] - v;   // exclusive
    }
    if (tid == SCAN_B - 1) g_partial[blockIdx.x] = sh[SCAN_B - 1];
}

__global__ void scan_top_kernel(int nb) {
    __shared__ int sh[1024];
    int tid = threadIdx.x;
    int v = (tid < nb) ? g_partial[tid] : 0;
    sh[tid] = v;
    __syncthreads();
    #pragma unroll
    for (int off = 1; off < 1024; off <<= 1) {
        int t = (tid >= off) ? sh[tid - off] : 0;
        __syncthreads();
        sh[tid] += t;
        __syncthreads();
    }
    if (tid < nb) g_partial[tid] = sh[tid] - v;  // exclusive
}

__global__ void scan_fix_kernel(int N, int E) {
    int i = blockIdx.x * blockDim.x + threadIdx.x;
    if (i < N) {
        int v = g_row_ptr[i] + g_partial[i >> 9];   // SCAN_B == 512
        g_row_ptr[i] = v;
        g_cursor[i]  = v;
    }
    if (i == 0) g_row_ptr[N] = E;
}

// ---------------------------------------------------------------------------
// 4) CSR fill: slot edges under their receiver
// ---------------------------------------------------------------------------
__global__ void fill_kernel(const int* __restrict__ s,
                            const int* __restrict__ r, int E) {
    int i = blockIdx.x * blockDim.x + threadIdx.x;
    if (i < E) {
        int pos = atomicAdd(&g_cursor[r[i]], 1);
        g_edge_src[pos] = s[i];
    }
}

// ---------------------------------------------------------------------------
// 5) GEMM + sender-degree pre-scale.
// BM=128, BN=128(full), BK=16, 256 threads, 8x8 register tile.
// smem traffic: 64B per 64 FMA per thread -> FMA-bound, not L1-bound.
// ---------------------------------------------------------------------------
__global__ __launch_bounds__(256) void gemm_scale_kernel(
    const float* __restrict__ x, const float* __restrict__ w,
    const float* __restrict__ bias, int M) {

    __shared__ float xs[16][128];   // [k][row]
    __shared__ float ws[16][128];   // [k][col]

    const int t   = threadIdx.x;
    const int ty  = t >> 4;         // 0..15 -> rows ty*8..+7
    const int tx  = t & 15;         // 0..15 -> cols tx*8..+7
    const int row0 = blockIdx.x * 128;

    float acc[8][8];
    #pragma unroll
    for (int i = 0; i < 8; i++)
        #pragma unroll
        for (int j = 0; j < 8; j++) acc[i][j] = 0.f;

    for (int k0 = 0; k0 < D; k0 += 16) {
        // x tile: 128 rows x 16 k = 512 float4; 256 threads x 2, transposed.
        #pragma unroll
        for (int u = 0; u < 2; u++) {
            int idx = t + u * 256;
            int lr  = idx >> 2;          // row 0..127
            int kq  = idx & 3;           // k-quad
            int gr  = row0 + lr;
            float4 xv = make_float4(0.f, 0.f, 0.f, 0.f);
            if (gr < M)
                xv = *(const float4*)&x[(size_t)gr * D + k0 + kq * 4];
            xs[kq * 4 + 0][lr] = xv.x;
            xs[kq * 4 + 1][lr] = xv.y;
            xs[kq * 4 + 2][lr] = xv.z;
            xs[kq * 4 + 3][lr] = xv.w;
        }
        // w tile: 16 x 128 = 512 float4; coalesced.
        #pragma unroll
        for (int u = 0; u < 2; u++) {
            int idx = t + u * 256;
            int kr = idx >> 5, c4 = idx & 31;
            *(float4*)&ws[kr][c4 * 4] =
                *(const float4*)&w[(size_t)(k0 + kr) * D + c4 * 4];
        }
        __syncthreads();

        #pragma unroll
        for (int k = 0; k < 16; k++) {
            float4 a0 = *(float4*)&xs[k][ty * 8];
            float4 a1 = *(float4*)&xs[k][ty * 8 + 4];
            float4 b0 = *(float4*)&ws[k][tx * 8];
            float4 b1 = *(float4*)&ws[k][tx * 8 + 4];
            float av[8] = {a0.x, a0.y, a0.z, a0.w, a1.x, a1.y, a1.z, a1.w};
            float bv[8] = {b0.x, b0.y, b0.z, b0.w, b1.x, b1.y, b1.z, b1.w};
            #pragma unroll
            for (int i = 0; i < 8; i++)
                #pragma unroll
                for (int j = 0; j < 8; j++)
                    acc[i][j] += av[i] * bv[j];
        }
        __syncthreads();
    }

    float bv[8];
    #pragma unroll
    for (int j = 0; j < 8; j++) bv[j] = bias[tx * 8 + j];

    #pragma unroll
    for (int i = 0; i < 8; i++) {
        int row = row0 + ty * 8 + i;
        if (row < M) {
            float sc = rsqrtf(fmaxf((float)g_cnt_s[row], 1.0f));
            #pragma unroll
            for (int j = 0; j < 8; j += 4) {
                float4 v;
                v.x = (acc[i][j + 0] + bv[j + 0]) * sc;
                v.y = (acc[i][j + 1] + bv[j + 1]) * sc;
                v.z = (acc[i][j + 2] + bv[j + 2]) * sc;
                v.w = (acc[i][j + 3] + bv[j + 3]) * sc;
                *(float4*)&g_h[(size_t)row * D + tx * 8 + j] = v;
            }
        }
    }
}

// ---------------------------------------------------------------------------
// 6) Gather: one warp per node. Lane l owns float4 l of the row.
// Register accumulation, no atomics; unroll-2 for MLP. Final scale fused.
// ---------------------------------------------------------------------------
__global__ __launch_bounds__(256) void gather_kernel(float* __restrict__ out,
                                                     int N) {
    int warp = blockIdx.x * (blockDim.x >> 5) + (threadIdx.x >> 5);
    int lane = threadIdx.x & 31;
    if (warp >= N) return;

    int beg = __ldg(&g_row_ptr[warp]);
    int end = __ldg(&g_row_ptr[warp + 1]);

    const float4* h4 = (const float4*)g_h;
    float4 acc = make_float4(0.f, 0.f, 0.f, 0.f);

    int e = beg;
    for (; e + 2 <= end; e += 2) {
        int s0 = __ldg(&g_edge_src[e]);
        int s1 = __ldg(&g_edge_src[e + 1]);
        float4 v0 = __ldg(&h4[(size_t)s0 * 32 + lane]);
        float4 v1 = __ldg(&h4[(size_t)s1 * 32 + lane]);
        acc.x += v0.x; acc.y += v0.y; acc.z += v0.z; acc.w += v0.w;
        acc.x += v1.x; acc.y += v1.y; acc.z += v1.z; acc.w += v1.w;
    }
    if (e < end) {
        int s0 = __ldg(&g_edge_src[e]);
        float4 v0 = __ldg(&h4[(size_t)s0 * 32 + lane]);
        acc.x += v0.x; acc.y += v0.y; acc.z += v0.z; acc.w += v0.w;
    }

    float sc = rsqrtf(fmaxf((float)__ldg(&g_cnt_r[warp]), 1.0f));
    acc.x *= sc; acc.y *= sc; acc.z *= sc; acc.w *= sc;
    ((float4*)out)[(size_t)warp * 32 + lane] = acc;
}

// ---------------------------------------------------------------------------
// Inputs (metadata order): x[N*128] f32, senders[E] i32, receivers[E] i32,
// n_node i32, weight[128*128] f32, bias[128] f32. Output: [N*128] f32.
// ---------------------------------------------------------------------------
extern "C" void kernel_launch(void* const* d_in, const int* in_sizes, int n_in,
                              void* d_out, int out_size) {
    const float* x       = (const float*)d_in[0];
    const int*   senders = (const int*)  d_in[1];
    const int*   recvs   = (const int*)  d_in[2];
    const float* weight  = (const float*)d_in[4];
    const float* bias    = (const float*)d_in[5];
    float*       out     = (float*)d_out;

    const int N = in_sizes[0] / D;
    const int E = in_sizes[1];
    const int NB = (N + SCAN_B - 1) / SCAN_B;   // scan blocks (<=1024)

    // degrees
    zero_cnt_kernel<<<(N + 255) / 256, 256>>>(N);
    hist_kernel<<<(E + 255) / 256, 256>>>(senders, recvs, E);

    // CSR build (receiver-major)
    scan_part_kernel<<<NB, SCAN_B>>>(N);
    scan_top_kernel<<<1, 1024>>>(NB);
    scan_fix_kernel<<<(N + 255) / 256, 256>>>(N, E);
    fill_kernel<<<(E + 255) / 256, 256>>>(senders, recvs, E);

    // GEMM + bias + sender-degree pre-scale -> g_h
    gemm_scale_kernel<<<(N + 127) / 128, 256>>>(x, weight, bias, N);

    // gather-aggregate + receiver-degree post-scale -> out
    gather_kernel<<<(N * 32 + 255) / 256, 256>>>(out, N);
}

// round 15
// speedup vs baseline: 2.7203x; 1.4642x over previous
#include <cuda_runtime.h>
#include <cuda_fp16.h>
#include <cuda_bf16.h>
#include <cstdint>

#define MAX_NODES 100000
#define MAX_EDGES 1600000
#define D 128
#define SCAN_B 512
#define PAD 136                       // halves per smem row (128 + 8)
#define GEMM_SMEM (3 * 128 * PAD * 2) // 104448 bytes

// ---------------------------------------------------------------------------
// Scratch (device globals; no allocations allowed anywhere).
// ---------------------------------------------------------------------------
__device__ __half g_h[MAX_NODES * D];         // fp16 h, pre-scaled by rsqrt(deg_s)
__device__ int    g_cnt_s[MAX_NODES];
__device__ int    g_cnt_r[MAX_NODES];
__device__ int    g_row_ptr[MAX_NODES + 1];
__device__ int    g_cursor[MAX_NODES];
__device__ int    g_edge_src[MAX_EDGES];
__device__ int    g_partial[1024];

// ---------------------------------------------------------------------------
__global__ void zero_cnt_kernel(int n) {
    int i = blockIdx.x * blockDim.x + threadIdx.x;
    if (i < n) { g_cnt_s[i] = 0; g_cnt_r[i] = 0; }
}

__global__ void hist_kernel(const int* __restrict__ s,
                            const int* __restrict__ r, int E) {
    int i = blockIdx.x * blockDim.x + threadIdx.x;
    if (i < E) {
        atomicAdd(&g_cnt_s[s[i]], 1);
        atomicAdd(&g_cnt_r[r[i]], 1);
    }
}

// ---------------------------------------------------------------------------
// exclusive scan of g_cnt_r -> g_row_ptr
// ---------------------------------------------------------------------------
__global__ void scan_part_kernel(int N) {
    __shared__ int sh[SCAN_B];
    int tid = threadIdx.x;
    int i = blockIdx.x * SCAN_B + tid;
    int v = (i < N) ? g_cnt_r[i] : 0;
    sh[tid] = v;
    __syncthreads();
    #pragma unroll
    for (int off = 1; off < SCAN_B; off <<= 1) {
        int t = (tid >= off) ? sh[tid - off] : 0;
        __syncthreads();
        sh[tid] += t;
        __syncthreads();
    }
    if (i < N) g_row_ptr[i] = sh[tid] - v;
    if (tid == SCAN_B - 1) g_partial[blockIdx.x] = sh[SCAN_B - 1];
}

__global__ void scan_top_kernel(int nb) {
    __shared__ int sh[256];
    int tid = threadIdx.x;
    int v = (tid < nb) ? g_partial[tid] : 0;
    sh[tid] = v;
    __syncthreads();
    #pragma unroll
    for (int off = 1; off < 256; off <<= 1) {
        int t = (tid >= off) ? sh[tid - off] : 0;
        __syncthreads();
        sh[tid] += t;
        __syncthreads();
    }
    if (tid < nb) g_partial[tid] = sh[tid] - v;
}

__global__ void scan_fix_kernel(int N, int E) {
    int i = blockIdx.x * blockDim.x + threadIdx.x;
    if (i < N) {
        int v = g_row_ptr[i] + g_partial[i >> 9];
        g_row_ptr[i] = v;
        g_cursor[i]  = v;
    }
    if (i == 0) g_row_ptr[N] = E;
}

__global__ void fill_kernel(const int* __restrict__ s,
                            const int* __restrict__ r, int E) {
    int i = blockIdx.x * blockDim.x + threadIdx.x;
    if (i < E) {
        int pos = atomicAdd(&g_cursor[r[i]], 1);
        g_edge_src[pos] = s[i];
    }
}

// ---------------------------------------------------------------------------
// GEMM via mma.sync.m16n8k16 (fp16 in, fp32 acc), W split into W_h + W_l so
// the only precision loss is x's single fp16 rounding (~2.8e-4 RMS).
// Block: 128 rows x 128 cols, K=128 fully smem-resident. 512 thr = 16 warps
// in 4x4 grid; warp tile 32x32 = (2 m16) x (4 n8); 8 k-steps of 16.
// ---------------------------------------------------------------------------
__device__ __forceinline__ void mma_16816(float* c, const uint32_t* a,
                                          const uint32_t* b) {
    asm volatile(
        "mma.sync.aligned.m16n8k16.row.col.f32.f16.f16.f32 "
        "{%0,%1,%2,%3}, {%4,%5,%6,%7}, {%8,%9}, {%0,%1,%2,%3};\n"
        : "+f"(c[0]), "+f"(c[1]), "+f"(c[2]), "+f"(c[3])
        : "r"(a[0]), "r"(a[1]), "r"(a[2]), "r"(a[3]),
          "r"(b[0]), "r"(b[1]));
}

__global__ __launch_bounds__(512) void gemm_mma_kernel(
    const float* __restrict__ x, const float* __restrict__ w,
    const float* __restrict__ bias, int M) {

    extern __shared__ __half smem_h[];
    __half* xs  = smem_h;                  // [128][PAD]  x tile (fp16)
    __half* whp = smem_h + 128 * PAD;      // [128][PAD]  W hi  (row = k)
    __half* wlp = whp    + 128 * PAD;      // [128][PAD]  W lo

    const int t    = threadIdx.x;
    const int row0 = blockIdx.x * 128;

    // ---- load + convert x tile (128x128 f32 -> fp16), zero-fill overhang ----
    #pragma unroll
    for (int u = 0; u < 8; u++) {
        int idx = u * 512 + t;             // float4 index 0..4095
        int r   = idx >> 5;                // row 0..127
        int c4  = idx & 31;                // float4 col
        float4 v = make_float4(0.f, 0.f, 0.f, 0.f);
        int gr = row0 + r;
        if (gr < M) v = *(const float4*)&x[(size_t)gr * D + c4 * 4];
        __half2 p0 = __floats2half2_rn(v.x, v.y);
        __half2 p1 = __floats2half2_rn(v.z, v.w);
        uint2 pk = make_uint2(*(uint32_t*)&p0, *(uint32_t*)&p1);
        *(uint2*)&xs[r * PAD + c4 * 4] = pk;
    }
    // ---- load + split W: w[k][n] -> wh (fp16) + wl (fp16 residual) ----
    #pragma unroll
    for (int u = 0; u < 8; u++) {
        int idx = u * 512 + t;
        int k   = idx >> 5;
        int n4  = idx & 31;
        float4 v = *(const float4*)&w[(size_t)k * D + n4 * 4];
        __half hx = __float2half_rn(v.x), hy = __float2half_rn(v.y);
        __half hz = __float2half_rn(v.z), hw = __float2half_rn(v.w);
        __half lx = __float2half_rn(v.x - __half2float(hx));
        __half ly = __float2half_rn(v.y - __half2float(hy));
        __half lz = __float2half_rn(v.z - __half2float(hz));
        __half lw = __float2half_rn(v.w - __half2float(hw));
        __half2 h0 = __halves2half2(hx, hy), h1 = __halves2half2(hz, hw);
        __half2 l0 = __halves2half2(lx, ly), l1 = __halves2half2(lz, lw);
        *(uint2*)&whp[k * PAD + n4 * 4] =
            make_uint2(*(uint32_t*)&h0, *(uint32_t*)&h1);
        *(uint2*)&wlp[k * PAD + n4 * 4] =
            make_uint2(*(uint32_t*)&l0, *(uint32_t*)&l1);
    }
    __syncthreads();

    const int wid  = t >> 5;
    const int lane = t & 31;
    const int g    = lane >> 2;            // 0..7
    const int tig  = lane & 3;             // 0..3
    const int m0   = (wid >> 2) * 32;      // warp row base 0/32/64/96
    const int n0   = (wid & 3)  * 32;      // warp col base 0/32/64/96

    float c[2][4][4];
    #pragma unroll
    for (int mt = 0; mt < 2; mt++)
        #pragma unroll
        for (int nt = 0; nt < 4; nt++)
            #pragma unroll
            for (int q = 0; q < 4; q++) c[mt][nt][q] = 0.f;

    #pragma unroll
    for (int kt = 0; kt < 8; kt++) {
        int k0 = kt * 16;
        // A fragments (row-major m16k16)
        uint32_t a[2][4];
        #pragma unroll
        for (int mt = 0; mt < 2; mt++) {
            int rb = m0 + mt * 16;
            a[mt][0] = *(uint32_t*)&xs[(rb + g)     * PAD + k0 + tig * 2];
            a[mt][1] = *(uint32_t*)&xs[(rb + g + 8) * PAD + k0 + tig * 2];
            a[mt][2] = *(uint32_t*)&xs[(rb + g)     * PAD + k0 + tig * 2 + 8];
            a[mt][3] = *(uint32_t*)&xs[(rb + g + 8) * PAD + k0 + tig * 2 + 8];
        }
        // B fragments (col-major k16n8)
        uint32_t bh[4][2], bl[4][2];
        #pragma unroll
        for (int nt = 0; nt < 4; nt++) {
            int n = n0 + nt * 8 + g;
            int k = k0 + tig * 2;
            __half2 p0 = __halves2half2(whp[(k)     * PAD + n],
                                        whp[(k + 1) * PAD + n]);
            __half2 p1 = __halves2half2(whp[(k + 8) * PAD + n],
                                        whp[(k + 9) * PAD + n]);
            bh[nt][0] = *(uint32_t*)&p0;
            bh[nt][1] = *(uint32_t*)&p1;
            __half2 q0 = __halves2half2(wlp[(k)     * PAD + n],
                                        wlp[(k + 1) * PAD + n]);
            __half2 q1 = __halves2half2(wlp[(k + 8) * PAD + n],
                                        wlp[(k + 9) * PAD + n]);
            bl[nt][0] = *(uint32_t*)&q0;
            bl[nt][1] = *(uint32_t*)&q1;
        }
        #pragma unroll
        for (int mt = 0; mt < 2; mt++)
            #pragma unroll
            for (int nt = 0; nt < 4; nt++) {
                mma_16816(c[mt][nt], a[mt], bh[nt]);
                mma_16816(c[mt][nt], a[mt], bl[nt]);
            }
    }

    // ---- epilogue: + bias, * rsqrt(max(deg_s,1)), fp16 store ----
    #pragma unroll
    for (int mt = 0; mt < 2; mt++) {
        int r0 = row0 + m0 + mt * 16 + g;      // rows for c[0],c[1]
        int r1 = r0 + 8;                       // rows for c[2],c[3]
        float s0 = (r0 < M) ? rsqrtf(fmaxf((float)g_cnt_s[r0], 1.0f)) : 0.f;
        float s1 = (r1 < M) ? rsqrtf(fmaxf((float)g_cnt_s[r1], 1.0f)) : 0.f;
        #pragma unroll
        for (int nt = 0; nt < 4; nt++) {
            int col = n0 + nt * 8 + tig * 2;
            float b0 = __ldg(&bias[col]);
            float b1 = __ldg(&bias[col + 1]);
            if (r0 < M) {
                __half2 p = __floats2half2_rn((c[mt][nt][0] + b0) * s0,
                                              (c[mt][nt][1] + b1) * s0);
                *(__half2*)&g_h[(size_t)r0 * D + col] = p;
            }
            if (r1 < M) {
                __half2 p = __floats2half2_rn((c[mt][nt][2] + b0) * s1,
                                              (c[mt][nt][3] + b1) * s1);
                *(__half2*)&g_h[(size_t)r1 * D + col] = p;
            }
        }
    }
}

// ---------------------------------------------------------------------------
// Gather: one warp per node, fp16 rows (256B), fp32 accumulation, no atomics.
// ---------------------------------------------------------------------------
__global__ __launch_bounds__(256) void gather_kernel(float* __restrict__ out,
                                                     int N) {
    int warp = blockIdx.x * (blockDim.x >> 5) + (threadIdx.x >> 5);
    int lane = threadIdx.x & 31;
    if (warp >= N) return;

    int beg = __ldg(&g_row_ptr[warp]);
    int end = __ldg(&g_row_ptr[warp + 1]);

    const uint2* h2 = (const uint2*)g_h;    // 32 uint2 per row
    float ax = 0.f, ay = 0.f, az = 0.f, aw = 0.f;

    int e = beg;
    for (; e + 2 <= end; e += 2) {
        int s0 = __ldg(&g_edge_src[e]);
        int s1 = __ldg(&g_edge_src[e + 1]);
        uint2 u0 = __ldg(&h2[(size_t)s0 * 32 + lane]);
        uint2 u1 = __ldg(&h2[(size_t)s1 * 32 + lane]);
        float2 f0 = __half22float2(*(__half2*)&u0.x);
        float2 f1 = __half22float2(*(__half2*)&u0.y);
        float2 f2 = __half22float2(*(__half2*)&u1.x);
        float2 f3 = __half22float2(*(__half2*)&u1.y);
        ax += f0.x + f2.x; ay += f0.y + f2.y;
        az += f1.x + f3.x; aw += f1.y + f3.y;
    }
    if (e < end) {
        int s0 = __ldg(&g_edge_src[e]);
        uint2 u0 = __ldg(&h2[(size_t)s0 * 32 + lane]);
        float2 f0 = __half22float2(*(__half2*)&u0.x);
        float2 f1 = __half22float2(*(__half2*)&u0.y);
        ax += f0.x; ay += f0.y; az += f1.x; aw += f1.y;
    }

    float sc = rsqrtf(fmaxf((float)__ldg(&g_cnt_r[warp]), 1.0f));
    float4 v = make_float4(ax * sc, ay * sc, az * sc, aw * sc);
    ((float4*)out)[(size_t)warp * 32 + lane] = v;
}

// ---------------------------------------------------------------------------
// Inputs (metadata order): x[N*128] f32, senders[E] i32, receivers[E] i32,
// n_node i32, weight[128*128] f32, bias[128] f32. Output: [N*128] f32.
// ---------------------------------------------------------------------------
extern "C" void kernel_launch(void* const* d_in, const int* in_sizes, int n_in,
                              void* d_out, int out_size) {
    const float* x       = (const float*)d_in[0];
    const int*   senders = (const int*)  d_in[1];
    const int*   recvs   = (const int*)  d_in[2];
    const float* weight  = (const float*)d_in[4];
    const float* bias    = (const float*)d_in[5];
    float*       out     = (float*)d_out;

    const int N = in_sizes[0] / D;
    const int E = in_sizes[1];
    const int NB = (N + SCAN_B - 1) / SCAN_B;

    // opt-in to >48KB dynamic smem. Unconditional (no static guards);
    // idempotent and not a stream op, so it is capture-safe.
    cudaFuncSetAttribute(gemm_mma_kernel,
                         cudaFuncAttributeMaxDynamicSharedMemorySize,
                         GEMM_SMEM);

    // degrees
    zero_cnt_kernel<<<(N + 255) / 256, 256>>>(N);
    hist_kernel<<<(E + 255) / 256, 256>>>(senders, recvs, E);

    // CSR build (receiver-major)
    scan_part_kernel<<<NB, SCAN_B>>>(N);
    scan_top_kernel<<<1, 256>>>(NB);
    scan_fix_kernel<<<(N + 255) / 256, 256>>>(N, E);
    fill_kernel<<<(E + 255) / 256, 256>>>(senders, recvs, E);

    // GEMM (tensor cores, W-split fp16) + bias + deg_s pre-scale -> g_h fp16
    gemm_mma_kernel<<<(N + 127) / 128, 512, GEMM_SMEM>>>(x, weight, bias, N);

    // gather-aggregate + deg_r post-scale -> out
    gather_kernel<<<(N * 32 + 255) / 256, 256>>>(out, N);
}